// round 5
// baseline (speedup 1.0000x reference)
#include <cuda_runtime.h>

#define ALPHA 26
#define TPB   128           // threads per block
#define NTOK  4             // tokens per thread
#define TOKB  (TPB * NTOK)  // 512 tokens per block
#define SEQ   8192

__global__ __launch_bounds__(TPB, 3)
void rotor_kernel(const float* __restrict__ x,
                  const float* __restrict__ rotor,
                  float* __restrict__ out)
{
    __shared__ __align__(16) float s_buf[TOKB * ALPHA];     // 53248 B
    __shared__ __align__(16) float s_rn[ALPHA][ALPHA + 2];  // padded rows, 112B stride
    __shared__ float s_inv[ALPHA];

    const int tid = threadIdx.x;

    // --- normalize rotor rows into smem ---
    if (tid < ALPHA) {
        float ss = 0.f;
        #pragma unroll
        for (int j = 0; j < ALPHA; ++j) {
            float v = rotor[tid * ALPHA + j];
            ss = fmaf(v, v, ss);
        }
        s_inv[tid] = rsqrtf(ss);
    }
    __syncthreads();
    for (int e = tid; e < ALPHA * ALPHA; e += TPB) {
        int r = e / ALPHA;
        s_rn[r][e - r * ALPHA] = rotor[e] * s_inv[r];
    }

    // --- coalesced float4 stage-in of this block's 512 tokens ---
    const size_t base = (size_t)blockIdx.x * (TOKB * ALPHA);
    const float4* __restrict__ xin4 = (const float4*)(x + base);
    float4* buf4 = (float4*)s_buf;
    const int n4 = TOKB * ALPHA / 4;                 // 3328
    #pragma unroll
    for (int e = tid; e < n4; e += TPB) buf4[e] = xin4[e];
    __syncthreads();

    // --- four tokens per thread ---
    int shift[NTOK];
    const float* __restrict__ xr[NTOK];
    #pragma unroll
    for (int k = 0; k < NTOK; ++k) {
        int t = blockIdx.x * TOKB + tid + k * TPB;
        shift[k] = (t & (SEQ - 1)) % ALPHA;
        xr[k] = s_buf + (tid + k * TPB) * ALPHA;
    }

    unsigned long long acc[NTOK][13];
    #pragma unroll
    for (int k = 0; k < NTOK; ++k)
        #pragma unroll
        for (int p = 0; p < 13; ++p) acc[k][p] = 0ull;

    #pragma unroll
    for (int r = 0; r < ALPHA; ++r) {
        // broadcast rn row r: 6 x LDS.128 + 1 x LDS.64 (warp-uniform)
        unsigned long long bb[13];
        const float4* __restrict__ rr4 = (const float4*)(&s_rn[r][0]);
        #pragma unroll
        for (int c = 0; c < 6; ++c) {
            float4 f = rr4[c];
            asm("mov.b64 %0, {%1, %2};" : "=l"(bb[2*c  ]) : "f"(f.x), "f"(f.y));
            asm("mov.b64 %0, {%1, %2};" : "=l"(bb[2*c+1]) : "f"(f.z), "f"(f.w));
        }
        {
            float2 f = *(const float2*)(&s_rn[r][24]);
            asm("mov.b64 %0, {%1, %2};" : "=l"(bb[12]) : "f"(f.x), "f"(f.y));
        }

        unsigned long long xx[NTOK];
        #pragma unroll
        for (int k = 0; k < NTOK; ++k) {
            int i = r - shift[k];
            i += (i >> 31) & ALPHA;                  // branchless mod 26
            float xv = xr[k][i];
            asm("mov.b64 %0, {%1, %1};" : "=l"(xx[k]) : "f"(xv));
        }

        #pragma unroll
        for (int k = 0; k < NTOK; ++k)
            #pragma unroll
            for (int p = 0; p < 13; ++p)
                asm("fma.rn.f32x2 %0, %1, %2, %0;"
                    : "+l"(acc[k][p]) : "l"(bb[p]), "l"(xx[k]));
    }

    __syncthreads();                                 // done reading s_buf as input

    // --- per-token softmax, write back to s_buf as float2 ---
    #pragma unroll
    for (int k = 0; k < NTOK; ++k) {
        float v[ALPHA];
        #pragma unroll
        for (int p = 0; p < 13; ++p)
            asm("mov.b64 {%0, %1}, %2;" : "=f"(v[2*p]), "=f"(v[2*p+1]) : "l"(acc[k][p]));

        float mx = v[0];
        #pragma unroll
        for (int j = 1; j < ALPHA; ++j) mx = fmaxf(mx, v[j]);
        float sum = 0.f;
        #pragma unroll
        for (int j = 0; j < ALPHA; ++j) {
            v[j] = __expf(v[j] - mx);
            sum += v[j];
        }
        const float inv = __fdividef(1.0f, sum);

        float2* w = (float2*)(s_buf + (tid + k * TPB) * ALPHA);  // 8B aligned
        #pragma unroll
        for (int p = 0; p < 13; ++p)
            w[p] = make_float2(v[2*p] * inv, v[2*p+1] * inv);
    }
    __syncthreads();

    // --- coalesced float4 stage-out ---
    float4* __restrict__ out4 = (float4*)(out + base);
    #pragma unroll
    for (int e = tid; e < n4; e += TPB) out4[e] = buf4[e];
}

extern "C" void kernel_launch(void* const* d_in, const int* in_sizes, int n_in,
                              void* d_out, int out_size)
{
    const float* x     = (const float*)d_in[0];   // [128, 8192, 26] f32
    const float* rotor = (const float*)d_in[1];   // [26, 26] f32
    float* out         = (float*)d_out;

    const int total_tokens = out_size / ALPHA;    // 1,048,576
    const int blocks = total_tokens / TOKB;       // 2048
    rotor_kernel<<<blocks, TPB>>>(x, rotor, out);
}